// round 2
// baseline (speedup 1.0000x reference)
#include <cuda_runtime.h>
#include <cuda_bf16.h>
#include <math.h>

// ---------------- problem constants ----------------
#define B_      64
#define V_      49
#define NPATCH  196
#define CIN     12
#define PSZ     16
#define IMG     224
#define ENC     768
#define DEC     512
#define NL      8
#define NH      16
#define HD      32          // DEC / NH
#define FFN     2048
#define OUTD    3072        // P*P*C_IN
#define ROWS_V  (B_ * V_)       // 3136
#define ROWS_N  (B_ * NPATCH)   // 12544

// ---------------- scratch (device globals; no allocation allowed) ----------------
__device__ float g_patch[ROWS_V * OUTD];     // 3136 x 3072
__device__ float g_dec  [ROWS_V * DEC];      // 3136 x 512
__device__ float g_h    [ROWS_N * DEC];      // 12544 x 512
__device__ float g_tmp  [ROWS_N * DEC];
__device__ float g_attn [ROWS_N * DEC];
__device__ float g_qkv  [ROWS_N * 3 * DEC];  // 12544 x 1536
__device__ float g_ffn  [ROWS_N * FFN];      // 12544 x 2048
__device__ int   g_visidx[B_ * V_];
__device__ int   g_src   [B_ * NPATCH];      // rank if visible else -1

// ---------------- mask scan ----------------
__global__ void scan_kernel(const int* __restrict__ mask) {
    int b = threadIdx.x;
    if (b >= B_) return;
    int cnt = 0;
    for (int n = 0; n < NPATCH; n++) {
        int m = mask[b * NPATCH + n];
        if (m == 0) {
            if (cnt < V_) g_visidx[b * V_ + cnt] = n;
            g_src[b * NPATCH + n] = (cnt < V_) ? cnt : (V_ - 1);
            cnt++;
        } else {
            g_src[b * NPATCH + n] = -1;
        }
    }
    // safety fill (should never trigger: exactly V_ visible per row)
    for (int c = cnt; c < V_; c++) g_visidx[b * V_ + c] = 0;
}

// ---------------- patchify visible patches ----------------
// feature order: (c, ph, pw); n = hp*14 + wp
__global__ void patchify_kernel(const float* __restrict__ x) {
    int r  = blockIdx.x;          // 0..3135
    int b  = r / V_;
    int n  = g_visidx[r];
    int hp = n / (IMG / PSZ);
    int wp = n % (IMG / PSZ);
    for (int f = threadIdx.x; f < OUTD; f += blockDim.x) {
        int c  = f >> 8;
        int ph = (f >> 4) & 15;
        int pw = f & 15;
        float v = x[((b * CIN + c) * IMG + hp * PSZ + ph) * IMG + wp * PSZ + pw];
        g_patch[r * OUTD + f] = v;
    }
}

// ---------------- assemble decoder input (scatter + mask token + pos) ----------------
__global__ void assemble_kernel(const float* __restrict__ mask_token,
                                const float* __restrict__ pos_embed) {
    int row = blockIdx.x;               // 0..12543
    int b = row / NPATCH;
    int n = row % NPATCH;
    int s = g_src[row];
    const float4* src = (s >= 0)
        ? (const float4*)&g_dec[(b * V_ + s) * DEC]
        : (const float4*)mask_token;
    const float4* pos = (const float4*)&pos_embed[n * DEC];
    float4* dst = (float4*)&g_h[row * DEC];
    int t = threadIdx.x;                // 128 threads, 4 floats each
    float4 a = src[t], p = pos[t];
    dst[t] = make_float4(a.x + p.x, a.y + p.y, a.z + p.z, a.w + p.w);
}

// ---------------- generic SGEMM: C = A(MxK) @ W(KxN) + bias [+resid] [gelu] ----------------
// All M % 64 == 0, N % 64 == 0, K % 16 == 0 for this problem.
__device__ __forceinline__ float gelu_exact(float v) {
    return 0.5f * v * (1.0f + erff(v * 0.7071067811865476f));
}

__global__ __launch_bounds__(256) void gemm_kernel(
    const float* __restrict__ A, const float* __restrict__ W,
    const float* __restrict__ bias, const float* __restrict__ resid,
    float* __restrict__ C, int M, int N, int K, int act)
{
    __shared__ float As[16][65];
    __shared__ float Bs[16][64];
    const int bn = blockIdx.x * 64;
    const int bm = blockIdx.y * 64;
    const int t  = threadIdx.x;
    const int tx = t & 15, ty = t >> 4;

    float acc[4][4] = {};

    const int a_m = t >> 2;          // 0..63
    const int a_k = (t & 3) * 4;     // 0,4,8,12
    const int b_k = t >> 4;          // 0..15
    const int b_n = (t & 15) * 4;

    const float* Aptr = A + (bm + a_m) * K + a_k;
    const float* Wptr = W + b_k * N + bn + b_n;

    for (int k0 = 0; k0 < K; k0 += 16) {
        float4 av = *(const float4*)(Aptr + k0);
        As[a_k + 0][a_m] = av.x;
        As[a_k + 1][a_m] = av.y;
        As[a_k + 2][a_m] = av.z;
        As[a_k + 3][a_m] = av.w;
        *(float4*)&Bs[b_k][b_n] = *(const float4*)(Wptr + k0 * N);
        __syncthreads();
        #pragma unroll
        for (int k = 0; k < 16; k++) {
            float a0 = As[k][ty * 4 + 0];
            float a1 = As[k][ty * 4 + 1];
            float a2 = As[k][ty * 4 + 2];
            float a3 = As[k][ty * 4 + 3];
            float4 bv = *(const float4*)&Bs[k][tx * 4];
            acc[0][0] += a0 * bv.x; acc[0][1] += a0 * bv.y; acc[0][2] += a0 * bv.z; acc[0][3] += a0 * bv.w;
            acc[1][0] += a1 * bv.x; acc[1][1] += a1 * bv.y; acc[1][2] += a1 * bv.z; acc[1][3] += a1 * bv.w;
            acc[2][0] += a2 * bv.x; acc[2][1] += a2 * bv.y; acc[2][2] += a2 * bv.z; acc[2][3] += a2 * bv.w;
            acc[3][0] += a3 * bv.x; acc[3][1] += a3 * bv.y; acc[3][2] += a3 * bv.z; acc[3][3] += a3 * bv.w;
        }
        __syncthreads();
    }

    #pragma unroll
    for (int i = 0; i < 4; i++) {
        int row = bm + ty * 4 + i;
        const float* rrow = resid ? (resid + row * N) : nullptr;
        float4 v;
        int col = bn + tx * 4;
        v.x = acc[i][0] + bias[col + 0];
        v.y = acc[i][1] + bias[col + 1];
        v.z = acc[i][2] + bias[col + 2];
        v.w = acc[i][3] + bias[col + 3];
        if (rrow) {
            float4 r = *(const float4*)(rrow + col);
            v.x += r.x; v.y += r.y; v.z += r.z; v.w += r.w;
        }
        if (act) {
            v.x = gelu_exact(v.x); v.y = gelu_exact(v.y);
            v.z = gelu_exact(v.z); v.w = gelu_exact(v.w);
        }
        *(float4*)(C + row * N + col) = v;
    }
}

// ---------------- layernorm over rows of 512 ----------------
__global__ __launch_bounds__(128) void ln_kernel(
    const float* __restrict__ in, float* __restrict__ out,
    const float* __restrict__ gamma, const float* __restrict__ beta)
{
    __shared__ float red[8];
    int row = blockIdx.x;
    int t = threadIdx.x;
    float4 v = ((const float4*)(in + row * DEC))[t];
    float s  = v.x + v.y + v.z + v.w;
    float sq = v.x * v.x + v.y * v.y + v.z * v.z + v.w * v.w;
    #pragma unroll
    for (int off = 16; off > 0; off >>= 1) {
        s  += __shfl_xor_sync(0xffffffff, s,  off);
        sq += __shfl_xor_sync(0xffffffff, sq, off);
    }
    int w = t >> 5;
    if ((t & 31) == 0) { red[w] = s; red[4 + w] = sq; }
    __syncthreads();
    s  = red[0] + red[1] + red[2] + red[3];
    sq = red[4] + red[5] + red[6] + red[7];
    float mu = s * (1.0f / DEC);
    float var = sq * (1.0f / DEC) - mu * mu;
    float rstd = rsqrtf(var + 1e-5f);
    float4 g = ((const float4*)gamma)[t];
    float4 b = ((const float4*)beta)[t];
    float4 o;
    o.x = (v.x - mu) * rstd * g.x + b.x;
    o.y = (v.y - mu) * rstd * g.y + b.y;
    o.z = (v.z - mu) * rstd * g.z + b.z;
    o.w = (v.w - mu) * rstd * g.w + b.w;
    ((float4*)(out + row * DEC))[t] = o;
}

// ---------------- attention: one block per (b, head) ----------------
// smem: K [196][33], V [196][32], P [8][196]
#define KSTRIDE 33
#define SM_K 0
#define SM_V (NPATCH * KSTRIDE)
#define SM_P (SM_V + NPATCH * HD)
#define ATTN_SMEM ((SM_P + 8 * NPATCH) * 4)

__global__ __launch_bounds__(256) void attn_kernel() {
    extern __shared__ float sm[];
    float* Ksm = sm + SM_K;
    float* Vsm = sm + SM_V;
    float* Psm = sm + SM_P;

    int bh = blockIdx.x;
    int b = bh >> 4;
    int h = bh & 15;
    const float* qkv = g_qkv + b * (NPATCH * 3 * DEC);
    int tid = threadIdx.x;

    for (int idx = tid; idx < NPATCH * HD; idx += 256) {
        int j = idx >> 5, d = idx & 31;
        Ksm[j * KSTRIDE + d] = qkv[j * (3 * DEC) + DEC     + h * HD + d];
        Vsm[j * HD      + d] = qkv[j * (3 * DEC) + 2 * DEC + h * HD + d];
    }
    __syncthreads();

    int warp = tid >> 5, lane = tid & 31;
    const float scale = 0.17677669529663687f;  // 1/sqrt(32)

    for (int i = warp; i < NPATCH; i += 8) {
        const float* q = qkv + i * (3 * DEC) + h * HD;
        float qr[HD];
        #pragma unroll
        for (int kk = 0; kk < HD; kk++) qr[kk] = q[kk];

        float s[7];
        float mx = -1e30f;
        #pragma unroll
        for (int jj = 0; jj < 7; jj++) {
            int j = jj * 32 + lane;
            float acc = -1e30f;
            if (j < NPATCH) {
                acc = 0.f;
                #pragma unroll
                for (int kk = 0; kk < HD; kk++) acc += qr[kk] * Ksm[j * KSTRIDE + kk];
                acc *= scale;
            }
            s[jj] = acc;
            mx = fmaxf(mx, acc);
        }
        #pragma unroll
        for (int off = 16; off > 0; off >>= 1)
            mx = fmaxf(mx, __shfl_xor_sync(0xffffffff, mx, off));

        float sum = 0.f;
        #pragma unroll
        for (int jj = 0; jj < 7; jj++) {
            int j = jj * 32 + lane;
            float p = (j < NPATCH) ? __expf(s[jj] - mx) : 0.f;
            if (j < NPATCH) Psm[warp * NPATCH + j] = p;
            sum += p;
        }
        #pragma unroll
        for (int off = 16; off > 0; off >>= 1)
            sum += __shfl_xor_sync(0xffffffff, sum, off);
        float inv = 1.0f / sum;
        __syncwarp();

        // lane == output dim d
        float acc = 0.f;
        for (int j = 0; j < NPATCH; j++)
            acc += Psm[warp * NPATCH + j] * Vsm[j * HD + lane];
        g_attn[(b * NPATCH + i) * DEC + h * HD + lane] = acc * inv;
        __syncwarp();
    }
}

// ---------------- host launcher ----------------
static inline void launch_gemm(const float* A, const float* W, const float* bias,
                               const float* resid, float* C, int M, int N, int K, int act) {
    dim3 grid(N / 64, M / 64);
    gemm_kernel<<<grid, 256>>>(A, W, bias, resid, C, M, N, K, act);
}

extern "C" void kernel_launch(void* const* d_in, const int* in_sizes, int n_in,
                              void* d_out, int out_size) {
    const float* x          = (const float*)d_in[0];
    const int*   mask       = (const int*)  d_in[1];
    // d_in[2] = n_visible (constant 49)
    const float* Wp         = (const float*)d_in[3];
    const float* bp         = (const float*)d_in[4];
    const float* We2d       = (const float*)d_in[5];
    const float* be2d       = (const float*)d_in[6];
    const float* mask_token = (const float*)d_in[7];
    const float* pos_embed  = (const float*)d_in[8];
    const float* Wqkv       = (const float*)d_in[9];
    const float* bqkv       = (const float*)d_in[10];
    const float* Wo         = (const float*)d_in[11];
    const float* bo         = (const float*)d_in[12];
    const float* ln1g       = (const float*)d_in[13];
    const float* ln1b       = (const float*)d_in[14];
    const float* W1         = (const float*)d_in[15];
    const float* b1         = (const float*)d_in[16];
    const float* W2         = (const float*)d_in[17];
    const float* b2         = (const float*)d_in[18];
    const float* ln2g       = (const float*)d_in[19];
    const float* ln2b       = (const float*)d_in[20];
    const float* Wr         = (const float*)d_in[21];
    const float* br         = (const float*)d_in[22];

    float* out = (float*)d_out;
    float* rec = out;                              // 12544 x 3072
    float* enc = out + (size_t)ROWS_N * OUTD;      // 3136 x 768

    float *p_patch, *p_dec, *p_h, *p_tmp, *p_attn, *p_qkv, *p_ffn;
    cudaGetSymbolAddress((void**)&p_patch, g_patch);
    cudaGetSymbolAddress((void**)&p_dec,   g_dec);
    cudaGetSymbolAddress((void**)&p_h,     g_h);
    cudaGetSymbolAddress((void**)&p_tmp,   g_tmp);
    cudaGetSymbolAddress((void**)&p_attn,  g_attn);
    cudaGetSymbolAddress((void**)&p_qkv,   g_qkv);
    cudaGetSymbolAddress((void**)&p_ffn,   g_ffn);

    cudaFuncSetAttribute(attn_kernel, cudaFuncAttributeMaxDynamicSharedMemorySize, ATTN_SMEM);

    // 1) mask scan + patchify
    scan_kernel<<<1, 64>>>(mask);
    patchify_kernel<<<ROWS_V, 256>>>(x);

    // 2) encoder projection -> encoded (written directly to output tail)
    launch_gemm(p_patch, Wp, bp, nullptr, enc, ROWS_V, ENC, OUTD, 0);

    // 3) enc->dec projection
    launch_gemm(enc, We2d, be2d, nullptr, p_dec, ROWS_V, DEC, ENC, 0);

    // 4) assemble full sequence with mask tokens + pos embed
    assemble_kernel<<<ROWS_N, 128>>>(mask_token, pos_embed);

    // 5) decoder layers
    for (int l = 0; l < NL; l++) {
        const float* wqkv = Wqkv + (size_t)l * DEC * 3 * DEC;
        const float* bq   = bqkv + (size_t)l * 3 * DEC;
        const float* wo   = Wo   + (size_t)l * DEC * DEC;
        const float* bol  = bo   + (size_t)l * DEC;
        const float* w1   = W1   + (size_t)l * DEC * FFN;
        const float* b1l  = b1   + (size_t)l * FFN;
        const float* w2   = W2   + (size_t)l * FFN * DEC;
        const float* b2l  = b2   + (size_t)l * DEC;

        launch_gemm(p_h, wqkv, bq, nullptr, p_qkv, ROWS_N, 3 * DEC, DEC, 0);
        attn_kernel<<<B_ * NH, 256, ATTN_SMEM>>>();
        launch_gemm(p_attn, wo, bol, p_h, p_tmp, ROWS_N, DEC, DEC, 0);
        ln_kernel<<<ROWS_N, 128>>>(p_tmp, p_h, ln1g + l * DEC, ln1b + l * DEC);
        launch_gemm(p_h, w1, b1l, nullptr, p_ffn, ROWS_N, FFN, DEC, 1);
        launch_gemm(p_ffn, w2, b2l, p_h, p_tmp, ROWS_N, DEC, FFN, 0);
        ln_kernel<<<ROWS_N, 128>>>(p_tmp, p_h, ln2g + l * DEC, ln2b + l * DEC);
    }

    // 6) reconstruction head
    launch_gemm(p_h, Wr, br, nullptr, rec, ROWS_N, OUTD, DEC, 0);
}

// round 4
// speedup vs baseline: 4.2458x; 4.2458x over previous
#include <cuda_runtime.h>
#include <cuda_bf16.h>
#include <cstdint>
#include <math.h>

// ---------------- problem constants ----------------
#define B_      64
#define V_      49
#define NPATCH  196
#define CIN     12
#define PSZ     16
#define IMG     224
#define ENC     768
#define DEC     512
#define NL      8
#define NH      16
#define HD      32
#define FFN     2048
#define OUTD    3072
#define ROWS_V  (B_ * V_)       // 3136
#define ROWS_N  (B_ * NPATCH)   // 12544

// ---------------- scratch ----------------
__device__ float g_patch[ROWS_V * OUTD];
__device__ float g_dec  [ROWS_V * DEC];
__device__ float g_h    [ROWS_N * DEC];
__device__ float g_tmp  [ROWS_N * DEC];
__device__ float g_attn [ROWS_N * DEC];
__device__ float g_qkv  [ROWS_N * 3 * DEC];
__device__ float g_ffn  [ROWS_N * FFN];
__device__ int   g_visidx[B_ * V_];
__device__ int   g_src   [B_ * NPATCH];

// ---------------- mask scan ----------------
__global__ void scan_kernel(const int* __restrict__ mask) {
    int b = threadIdx.x;
    if (b >= B_) return;
    int cnt = 0;
    for (int n = 0; n < NPATCH; n++) {
        int m = mask[b * NPATCH + n];
        if (m == 0) {
            if (cnt < V_) g_visidx[b * V_ + cnt] = n;
            g_src[b * NPATCH + n] = (cnt < V_) ? cnt : (V_ - 1);
            cnt++;
        } else {
            g_src[b * NPATCH + n] = -1;
        }
    }
    for (int c = cnt; c < V_; c++) g_visidx[b * V_ + c] = 0;
}

// ---------------- patchify ----------------
__global__ void patchify_kernel(const float* __restrict__ x) {
    int r  = blockIdx.x;
    int b  = r / V_;
    int n  = g_visidx[r];
    int hp = n / (IMG / PSZ);
    int wp = n % (IMG / PSZ);
    for (int f = threadIdx.x; f < OUTD; f += blockDim.x) {
        int c  = f >> 8;
        int ph = (f >> 4) & 15;
        int pw = f & 15;
        float v = x[((b * CIN + c) * IMG + hp * PSZ + ph) * IMG + wp * PSZ + pw];
        g_patch[r * OUTD + f] = v;
    }
}

// ---------------- assemble ----------------
__global__ void assemble_kernel(const float* __restrict__ mask_token,
                                const float* __restrict__ pos_embed) {
    int row = blockIdx.x;
    int b = row / NPATCH;
    int n = row % NPATCH;
    int s = g_src[row];
    const float4* src = (s >= 0)
        ? (const float4*)&g_dec[(b * V_ + s) * DEC]
        : (const float4*)mask_token;
    const float4* pos = (const float4*)&pos_embed[n * DEC];
    float4* dst = (float4*)&g_h[row * DEC];
    int t = threadIdx.x;
    float4 a = src[t], p = pos[t];
    dst[t] = make_float4(a.x + p.x, a.y + p.y, a.z + p.z, a.w + p.w);
}

// ---------------- tf32 tensor-core GEMM ----------------
// C(MxN) = A(MxK) @ W(KxN) + bias [+resid] [gelu]
// BM=128 BN=128 BK=32, 256 threads, warp grid 2x4, warp tile 64x32.
#define BM 128
#define BN 128
#define BK 32
#define ASTRIDE 36
#define BSTRIDE 136
#define ABUF (BM * ASTRIDE)          // 4608 floats
#define BBUF (BK * BSTRIDE)          // 4352 floats
#define GEMM_SMEM ((2 * ABUF + 2 * BBUF) * 4)   // 71680 B

__device__ __forceinline__ float gelu_exact(float v) {
    return 0.5f * v * (1.0f + erff(v * 0.7071067811865476f));
}

__device__ __forceinline__ uint32_t f2tf32(float x) {
    uint32_t y;
    asm("cvt.rna.tf32.f32 %0, %1;" : "=r"(y) : "f"(x));
    return y;
}

__device__ __forceinline__ void cp_async16(void* smem_dst, const void* gmem_src, bool pred) {
    uint32_t saddr = (uint32_t)__cvta_generic_to_shared(smem_dst);
    int sz = pred ? 16 : 0;
    asm volatile("cp.async.cg.shared.global [%0], [%1], 16, %2;\n"
                 :: "r"(saddr), "l"(gmem_src), "r"(sz));
}

__device__ __forceinline__ void mma_tf32(float* c, const uint32_t* a, const uint32_t* b) {
    asm volatile(
        "mma.sync.aligned.m16n8k8.row.col.f32.tf32.tf32.f32 "
        "{%0,%1,%2,%3}, {%4,%5,%6,%7}, {%8,%9}, {%0,%1,%2,%3};"
        : "+f"(c[0]), "+f"(c[1]), "+f"(c[2]), "+f"(c[3])
        : "r"(a[0]), "r"(a[1]), "r"(a[2]), "r"(a[3]), "r"(b[0]), "r"(b[1]));
}

__device__ __forceinline__ void gemm_load_chunk(
    const float* __restrict__ A, const float* __restrict__ W,
    float* As, float* Bs, int buf, int k0,
    int bm, int bn, int M, int N, int K, int t)
{
    float* Ab = As + buf * ABUF;
    float* Bb = Bs + buf * BBUF;
    #pragma unroll
    for (int i = 0; i < 4; i++) {
        int rl = (t >> 3) + i * 32;       // 0..127
        int c4 = (t & 7) * 4;             // 0..28
        int grow = bm + rl;
        bool ok = grow < M;
        const float* src = A + (size_t)(ok ? grow : (M - 1)) * K + k0 + c4;
        cp_async16(Ab + rl * ASTRIDE + c4, src, ok);
    }
    #pragma unroll
    for (int i = 0; i < 4; i++) {
        int kl = (t >> 5) + i * 8;        // 0..31
        int n4 = (t & 31) * 4;            // 0..124
        const float* src = W + (size_t)(k0 + kl) * N + bn + n4;
        cp_async16(Bb + kl * BSTRIDE + n4, src, true);
    }
    asm volatile("cp.async.commit_group;\n");
}

__global__ __launch_bounds__(256, 2) void gemm_tc_kernel(
    const float* __restrict__ A, const float* __restrict__ W,
    const float* __restrict__ bias, const float* __restrict__ resid,
    float* __restrict__ C, int M, int N, int K, int act)
{
    extern __shared__ float sm[];
    float* As = sm;
    float* Bs = sm + 2 * ABUF;

    const int t = threadIdx.x;
    const int bn = blockIdx.x * BN;
    const int bm = blockIdx.y * BM;
    const int warp = t >> 5, lane = t & 31;
    const int wm = warp >> 2, wn = warp & 3;
    const int lq = lane >> 2, lr = lane & 3;

    float acc[4][4][4] = {};

    const int nch = K / BK;
    gemm_load_chunk(A, W, As, Bs, 0, 0, bm, bn, M, N, K, t);

    for (int ch = 0; ch < nch; ch++) {
        int buf = ch & 1;
        if (ch + 1 < nch) {
            gemm_load_chunk(A, W, As, Bs, buf ^ 1, (ch + 1) * BK, bm, bn, M, N, K, t);
            asm volatile("cp.async.wait_group 1;\n");
        } else {
            asm volatile("cp.async.wait_group 0;\n");
        }
        __syncthreads();

        const float* Ab = As + buf * ABUF;
        const float* Bb = Bs + buf * BBUF;

        #pragma unroll
        for (int ks = 0; ks < 4; ks++) {
            const int k = ks * 8;
            uint32_t af[4][4];
            uint32_t bf[4][2];
            #pragma unroll
            for (int mi = 0; mi < 4; mi++) {
                const float* p = Ab + (wm * 64 + mi * 16 + lq) * ASTRIDE + k + lr;
                af[mi][0] = f2tf32(p[0]);
                af[mi][1] = f2tf32(p[8 * ASTRIDE]);
                af[mi][2] = f2tf32(p[4]);
                af[mi][3] = f2tf32(p[8 * ASTRIDE + 4]);
            }
            #pragma unroll
            for (int ni = 0; ni < 4; ni++) {
                const float* p = Bb + (k + lr) * BSTRIDE + wn * 32 + ni * 8 + lq;
                bf[ni][0] = f2tf32(p[0]);
                bf[ni][1] = f2tf32(p[4 * BSTRIDE]);
            }
            #pragma unroll
            for (int mi = 0; mi < 4; mi++)
                #pragma unroll
                for (int ni = 0; ni < 4; ni++)
                    mma_tf32(acc[mi][ni], af[mi], bf[ni]);
        }
        __syncthreads();
    }

    // epilogue
    #pragma unroll
    for (int mi = 0; mi < 4; mi++) {
        int r0 = bm + wm * 64 + mi * 16 + lq;
        int r1 = r0 + 8;
        #pragma unroll
        for (int ni = 0; ni < 4; ni++) {
            int col = bn + wn * 32 + ni * 8 + lr * 2;
            float bx = bias[col], by = bias[col + 1];
            float* a4 = acc[mi][ni];
            if (r0 < M) {
                float vx = a4[0] + bx, vy = a4[1] + by;
                if (resid) {
                    const float* rr = resid + (size_t)r0 * N + col;
                    vx += rr[0]; vy += rr[1];
                }
                if (act) { vx = gelu_exact(vx); vy = gelu_exact(vy); }
                *(float2*)(C + (size_t)r0 * N + col) = make_float2(vx, vy);
            }
            if (r1 < M) {
                float vx = a4[2] + bx, vy = a4[3] + by;
                if (resid) {
                    const float* rr = resid + (size_t)r1 * N + col;
                    vx += rr[0]; vy += rr[1];
                }
                if (act) { vx = gelu_exact(vx); vy = gelu_exact(vy); }
                *(float2*)(C + (size_t)r1 * N + col) = make_float2(vx, vy);
            }
        }
    }
}

// ---------------- layernorm ----------------
__global__ __launch_bounds__(128) void ln_kernel(
    const float* __restrict__ in, float* __restrict__ out,
    const float* __restrict__ gamma, const float* __restrict__ beta)
{
    __shared__ float red[8];
    int row = blockIdx.x;
    int t = threadIdx.x;
    float4 v = ((const float4*)(in + (size_t)row * DEC))[t];
    float s  = v.x + v.y + v.z + v.w;
    float sq = v.x * v.x + v.y * v.y + v.z * v.z + v.w * v.w;
    #pragma unroll
    for (int off = 16; off > 0; off >>= 1) {
        s  += __shfl_xor_sync(0xffffffff, s,  off);
        sq += __shfl_xor_sync(0xffffffff, sq, off);
    }
    int w = t >> 5;
    if ((t & 31) == 0) { red[w] = s; red[4 + w] = sq; }
    __syncthreads();
    s  = red[0] + red[1] + red[2] + red[3];
    sq = red[4] + red[5] + red[6] + red[7];
    float mu = s * (1.0f / DEC);
    float var = sq * (1.0f / DEC) - mu * mu;
    float rstd = rsqrtf(var + 1e-5f);
    float4 g = ((const float4*)gamma)[t];
    float4 b = ((const float4*)beta)[t];
    float4 o;
    o.x = (v.x - mu) * rstd * g.x + b.x;
    o.y = (v.y - mu) * rstd * g.y + b.y;
    o.z = (v.z - mu) * rstd * g.z + b.z;
    o.w = (v.w - mu) * rstd * g.w + b.w;
    ((float4*)(out + (size_t)row * DEC))[t] = o;
}

// ---------------- attention ----------------
#define KSTRIDE 33
#define SM_K 0
#define SM_V (NPATCH * KSTRIDE)
#define SM_P (SM_V + NPATCH * HD)
#define ATTN_SMEM ((SM_P + 8 * NPATCH) * 4)

__global__ __launch_bounds__(256) void attn_kernel() {
    extern __shared__ float smf[];
    float* Ksm = smf + SM_K;
    float* Vsm = smf + SM_V;
    float* Psm = smf + SM_P;

    int bh = blockIdx.x;
    int b = bh >> 4;
    int h = bh & 15;
    const float* qkv = g_qkv + (size_t)b * (NPATCH * 3 * DEC);
    int tid = threadIdx.x;

    for (int idx = tid; idx < NPATCH * HD; idx += 256) {
        int j = idx >> 5, d = idx & 31;
        Ksm[j * KSTRIDE + d] = qkv[j * (3 * DEC) + DEC     + h * HD + d];
        Vsm[j * HD      + d] = qkv[j * (3 * DEC) + 2 * DEC + h * HD + d];
    }
    __syncthreads();

    int warp = tid >> 5, lane = tid & 31;
    const float scale = 0.17677669529663687f;

    for (int i = warp; i < NPATCH; i += 8) {
        const float* q = qkv + i * (3 * DEC) + h * HD;
        float qr[HD];
        #pragma unroll
        for (int kk = 0; kk < HD; kk++) qr[kk] = q[kk];

        float s[7];
        float mx = -1e30f;
        #pragma unroll
        for (int jj = 0; jj < 7; jj++) {
            int j = jj * 32 + lane;
            float acc = -1e30f;
            if (j < NPATCH) {
                acc = 0.f;
                #pragma unroll
                for (int kk = 0; kk < HD; kk++) acc += qr[kk] * Ksm[j * KSTRIDE + kk];
                acc *= scale;
            }
            s[jj] = acc;
            mx = fmaxf(mx, acc);
        }
        #pragma unroll
        for (int off = 16; off > 0; off >>= 1)
            mx = fmaxf(mx, __shfl_xor_sync(0xffffffff, mx, off));

        float sum = 0.f;
        #pragma unroll
        for (int jj = 0; jj < 7; jj++) {
            int j = jj * 32 + lane;
            float p = (j < NPATCH) ? __expf(s[jj] - mx) : 0.f;
            if (j < NPATCH) Psm[warp * NPATCH + j] = p;
            sum += p;
        }
        #pragma unroll
        for (int off = 16; off > 0; off >>= 1)
            sum += __shfl_xor_sync(0xffffffff, sum, off);
        float inv = 1.0f / sum;
        __syncwarp();

        float acc = 0.f;
        for (int j = 0; j < NPATCH; j++)
            acc += Psm[warp * NPATCH + j] * Vsm[j * HD + lane];
        g_attn[((size_t)b * NPATCH + i) * DEC + h * HD + lane] = acc * inv;
        __syncwarp();
    }
}

// ---------------- host launcher ----------------
static inline void launch_gemm(const float* A, const float* W, const float* bias,
                               const float* resid, float* C, int M, int N, int K, int act) {
    dim3 grid(N / BN, (M + BM - 1) / BM);
    gemm_tc_kernel<<<grid, 256, GEMM_SMEM>>>(A, W, bias, resid, C, M, N, K, act);
}

extern "C" void kernel_launch(void* const* d_in, const int* in_sizes, int n_in,
                              void* d_out, int out_size) {
    const float* x          = (const float*)d_in[0];
    const int*   mask       = (const int*)  d_in[1];
    const float* Wp         = (const float*)d_in[3];
    const float* bp         = (const float*)d_in[4];
    const float* We2d       = (const float*)d_in[5];
    const float* be2d       = (const float*)d_in[6];
    const float* mask_token = (const float*)d_in[7];
    const float* pos_embed  = (const float*)d_in[8];
    const float* Wqkv       = (const float*)d_in[9];
    const float* bqkv       = (const float*)d_in[10];
    const float* Wo         = (const float*)d_in[11];
    const float* bo         = (const float*)d_in[12];
    const float* ln1g       = (const float*)d_in[13];
    const float* ln1b       = (const float*)d_in[14];
    const float* W1         = (const float*)d_in[15];
    const float* b1         = (const float*)d_in[16];
    const float* W2         = (const float*)d_in[17];
    const float* b2         = (const float*)d_in[18];
    const float* ln2g       = (const float*)d_in[19];
    const float* ln2b       = (const float*)d_in[20];
    const float* Wr         = (const float*)d_in[21];
    const float* br         = (const float*)d_in[22];

    float* out = (float*)d_out;
    float* rec = out;
    float* enc = out + (size_t)ROWS_N * OUTD;

    float *p_patch, *p_dec, *p_h, *p_tmp, *p_attn, *p_qkv, *p_ffn;
    cudaGetSymbolAddress((void**)&p_patch, g_patch);
    cudaGetSymbolAddress((void**)&p_dec,   g_dec);
    cudaGetSymbolAddress((void**)&p_h,     g_h);
    cudaGetSymbolAddress((void**)&p_tmp,   g_tmp);
    cudaGetSymbolAddress((void**)&p_attn,  g_attn);
    cudaGetSymbolAddress((void**)&p_qkv,   g_qkv);
    cudaGetSymbolAddress((void**)&p_ffn,   g_ffn);

    cudaFuncSetAttribute(attn_kernel, cudaFuncAttributeMaxDynamicSharedMemorySize, ATTN_SMEM);
    cudaFuncSetAttribute(gemm_tc_kernel, cudaFuncAttributeMaxDynamicSharedMemorySize, GEMM_SMEM);

    scan_kernel<<<1, 64>>>(mask);
    patchify_kernel<<<ROWS_V, 256>>>(x);

    launch_gemm(p_patch, Wp, bp, nullptr, enc, ROWS_V, ENC, OUTD, 0);
    launch_gemm(enc, We2d, be2d, nullptr, p_dec, ROWS_V, DEC, ENC, 0);
    assemble_kernel<<<ROWS_N, 128>>>(mask_token, pos_embed);

    for (int l = 0; l < NL; l++) {
        const float* wqkv = Wqkv + (size_t)l * DEC * 3 * DEC;
        const float* bq   = bqkv + (size_t)l * 3 * DEC;
        const float* wo   = Wo   + (size_t)l * DEC * DEC;
        const float* bol  = bo   + (size_t)l * DEC;
        const float* w1   = W1   + (size_t)l * DEC * FFN;
        const float* b1l  = b1   + (size_t)l * FFN;
        const float* w2   = W2   + (size_t)l * FFN * DEC;
        const float* b2l  = b2   + (size_t)l * DEC;

        launch_gemm(p_h, wqkv, bq, nullptr, p_qkv, ROWS_N, 3 * DEC, DEC, 0);
        attn_kernel<<<B_ * NH, 256, ATTN_SMEM>>>();
        launch_gemm(p_attn, wo, bol, p_h, p_tmp, ROWS_N, DEC, DEC, 0);
        ln_kernel<<<ROWS_N, 128>>>(p_tmp, p_h, ln1g + l * DEC, ln1b + l * DEC);
        launch_gemm(p_h, w1, b1l, nullptr, p_ffn, ROWS_N, FFN, DEC, 1);
        launch_gemm(p_ffn, w2, b2l, p_h, p_tmp, ROWS_N, DEC, FFN, 0);
        ln_kernel<<<ROWS_N, 128>>>(p_tmp, p_h, ln2g + l * DEC, ln2b + l * DEC);
    }

    launch_gemm(p_h, Wr, br, nullptr, rec, ROWS_N, OUTD, DEC, 0);
}

// round 6
// speedup vs baseline: 4.4692x; 1.0526x over previous
#include <cuda_runtime.h>
#include <cuda_bf16.h>
#include <cstdint>
#include <math.h>

// ---------------- problem constants ----------------
#define B_      64
#define V_      49
#define NPATCH  196
#define CIN     12
#define PSZ     16
#define IMG     224
#define ENC     768
#define DEC     512
#define NL      8
#define NH      16
#define HD      32
#define FFN     2048
#define OUTD    3072
#define ROWS_V  (B_ * V_)       // 3136
#define ROWS_N  (B_ * NPATCH)   // 12544

// ---------------- scratch ----------------
__device__ float g_patch[ROWS_V * OUTD];
__device__ float g_encr [ROWS_V * ENC];
__device__ float g_dec  [ROWS_V * DEC];
__device__ float g_h    [ROWS_N * DEC];
__device__ float g_hr   [ROWS_N * DEC];
__device__ float g_tmp  [ROWS_N * DEC];
__device__ float g_attn [ROWS_N * DEC];
__device__ float g_qkv  [ROWS_N * 3 * DEC];
__device__ float g_ffn  [ROWS_N * FFN];
__device__ float g_wt   [29491200];          // tf32-rounded weights (same [K,N] layout)
__device__ int   g_visidx[B_ * V_];
__device__ int   g_src   [B_ * NPATCH];

// weight-scratch offsets (floats)
#define WT_WP   0
#define WT_E2D  2359296
#define WT_QKV  2752512
#define WT_O    9043968
#define WT_W1   11141120
#define WT_W2   19529728
#define WT_R    27918336

// ---------------- helpers ----------------
__device__ __forceinline__ float rna_tf32(float x) {
    uint32_t y;
    asm("cvt.rna.tf32.f32 %0, %1;" : "=r"(y) : "f"(x));
    return __uint_as_float(y);
}
__device__ __forceinline__ float gelu_exact(float v) {
    return 0.5f * v * (1.0f + erff(v * 0.7071067811865476f));
}
__device__ __forceinline__ void cp_async16(void* smem_dst, const void* gmem_src, bool pred) {
    uint32_t saddr = (uint32_t)__cvta_generic_to_shared(smem_dst);
    int sz = pred ? 16 : 0;
    asm volatile("cp.async.cg.shared.global [%0], [%1], 16, %2;\n"
                 :: "r"(saddr), "l"(gmem_src), "r"(sz));
}
__device__ __forceinline__ void mma_tf32(float* c, const uint32_t* a, const uint32_t* b) {
    asm volatile(
        "mma.sync.aligned.m16n8k8.row.col.f32.tf32.tf32.f32 "
        "{%0,%1,%2,%3}, {%4,%5,%6,%7}, {%8,%9}, {%0,%1,%2,%3};"
        : "+f"(c[0]), "+f"(c[1]), "+f"(c[2]), "+f"(c[3])
        : "r"(a[0]), "r"(a[1]), "r"(a[2]), "r"(a[3]), "r"(b[0]), "r"(b[1]));
}

// ---------------- weight round-copy (values become exactly tf32-representable) ----------------
__global__ void round_copy(const float* __restrict__ src, float* __restrict__ dst, int n4) {
    int i = blockIdx.x * blockDim.x + threadIdx.x;
    if (i >= n4) return;
    float4 v = ((const float4*)src)[i];
    ((float4*)dst)[i] = make_float4(rna_tf32(v.x), rna_tf32(v.y), rna_tf32(v.z), rna_tf32(v.w));
}

// ---------------- mask scan ----------------
__global__ void scan_kernel(const int* __restrict__ mask) {
    int b = threadIdx.x;
    if (b >= B_) return;
    int cnt = 0;
    for (int n = 0; n < NPATCH; n++) {
        int m = mask[b * NPATCH + n];
        if (m == 0) {
            if (cnt < V_) g_visidx[b * V_ + cnt] = n;
            g_src[b * NPATCH + n] = (cnt < V_) ? cnt : (V_ - 1);
            cnt++;
        } else {
            g_src[b * NPATCH + n] = -1;
        }
    }
    for (int c = cnt; c < V_; c++) g_visidx[b * V_ + c] = 0;
}

// ---------------- patchify (rounded: feeds GEMM A only) ----------------
__global__ void patchify_kernel(const float* __restrict__ x) {
    int r  = blockIdx.x;
    int b  = r / V_;
    int n  = g_visidx[r];
    int hp = n / (IMG / PSZ);
    int wp = n % (IMG / PSZ);
    for (int f = threadIdx.x; f < OUTD; f += blockDim.x) {
        int c  = f >> 8;
        int ph = (f >> 4) & 15;
        int pw = f & 15;
        float v = x[((b * CIN + c) * IMG + hp * PSZ + ph) * IMG + wp * PSZ + pw];
        g_patch[r * OUTD + f] = rna_tf32(v);
    }
}

// ---------------- assemble: fp32 residual + rounded GEMM-A copy ----------------
__global__ void assemble_kernel(const float* __restrict__ mask_token,
                                const float* __restrict__ pos_embed) {
    int row = blockIdx.x;
    int b = row / NPATCH;
    int n = row % NPATCH;
    int s = g_src[row];
    const float4* src = (s >= 0)
        ? (const float4*)&g_dec[(b * V_ + s) * DEC]
        : (const float4*)mask_token;
    const float4* pos = (const float4*)&pos_embed[n * DEC];
    int t = threadIdx.x;
    float4 a = src[t], p = pos[t];
    float4 v = make_float4(a.x + p.x, a.y + p.y, a.z + p.z, a.w + p.w);
    ((float4*)&g_h[(size_t)row * DEC])[t] = v;
    ((float4*)&g_hr[(size_t)row * DEC])[t] =
        make_float4(rna_tf32(v.x), rna_tf32(v.y), rna_tf32(v.z), rna_tf32(v.w));
}

// ---------------- tf32 tensor-core GEMM (pre-rounded operands; no in-loop cvt) ----------------
// C(MxN) = A(MxK) @ W(KxN) + bias [+resid] [gelu] ; optional rounded copy Cr.
#define BM 128
#define BN 128
#define BK 32
#define ASTRIDE 36
#define BSTRIDE 136
#define ABUF (BM * ASTRIDE)          // 4608 floats
#define BBUF (BK * BSTRIDE)          // 4352 floats
#define GEMM_SMEM ((2 * ABUF + 2 * BBUF) * 4)   // 71680 B
#define FLAG_GELU  1
#define FLAG_ROUND 2

__device__ __forceinline__ void gemm_load_chunk(
    const float* __restrict__ A, const float* __restrict__ W,
    float* As, float* Bs, int buf, int k0,
    int bm, int bn, int M, int N, int K, int t)
{
    float* Ab = As + buf * ABUF;
    float* Bb = Bs + buf * BBUF;
    #pragma unroll
    for (int i = 0; i < 4; i++) {
        int rl = (t >> 3) + i * 32;       // 0..127
        int c4 = (t & 7) * 4;             // 0..28
        int grow = bm + rl;
        bool ok = grow < M;
        const float* src = A + (size_t)(ok ? grow : (M - 1)) * K + k0 + c4;
        cp_async16(Ab + rl * ASTRIDE + c4, src, ok);
    }
    #pragma unroll
    for (int i = 0; i < 4; i++) {
        int kl = (t >> 5) + i * 8;        // 0..31
        int n4 = (t & 31) * 4;            // 0..124
        const float* src = W + (size_t)(k0 + kl) * N + bn + n4;
        cp_async16(Bb + kl * BSTRIDE + n4, src, true);
    }
    asm volatile("cp.async.commit_group;\n");
}

__global__ __launch_bounds__(256, 2) void gemm_tc_kernel(
    const float* __restrict__ A, const float* __restrict__ W,
    const float* __restrict__ bias, const float* __restrict__ resid,
    float* __restrict__ C, float* __restrict__ Cr,
    int M, int N, int K, int flags)
{
    extern __shared__ float sm[];
    float* As = sm;
    float* Bs = sm + 2 * ABUF;

    const int t = threadIdx.x;
    const int bn = blockIdx.x * BN;
    const int bm = blockIdx.y * BM;
    const int warp = t >> 5, lane = t & 31;
    const int wm = warp >> 2, wn = warp & 3;
    const int lq = lane >> 2, lr = lane & 3;

    float acc[4][4][4] = {};

    const int nch = K / BK;
    gemm_load_chunk(A, W, As, Bs, 0, 0, bm, bn, M, N, K, t);

    for (int ch = 0; ch < nch; ch++) {
        int buf = ch & 1;
        if (ch + 1 < nch) {
            gemm_load_chunk(A, W, As, Bs, buf ^ 1, (ch + 1) * BK, bm, bn, M, N, K, t);
            asm volatile("cp.async.wait_group 1;\n");
        } else {
            asm volatile("cp.async.wait_group 0;\n");
        }
        __syncthreads();

        const uint32_t* Ab = (const uint32_t*)(As + buf * ABUF);
        const uint32_t* Bb = (const uint32_t*)(Bs + buf * BBUF);

        #pragma unroll
        for (int ks = 0; ks < 4; ks++) {
            const int k = ks * 8;
            uint32_t af[4][4];
            uint32_t bf[4][2];
            #pragma unroll
            for (int mi = 0; mi < 4; mi++) {
                const uint32_t* p = Ab + (wm * 64 + mi * 16 + lq) * ASTRIDE + k + lr;
                af[mi][0] = p[0];
                af[mi][1] = p[8 * ASTRIDE];
                af[mi][2] = p[4];
                af[mi][3] = p[8 * ASTRIDE + 4];
            }
            #pragma unroll
            for (int ni = 0; ni < 4; ni++) {
                const uint32_t* p = Bb + (k + lr) * BSTRIDE + wn * 32 + ni * 8 + lq;
                bf[ni][0] = p[0];
                bf[ni][1] = p[4 * BSTRIDE];
            }
            #pragma unroll
            for (int mi = 0; mi < 4; mi++)
                #pragma unroll
                for (int ni = 0; ni < 4; ni++)
                    mma_tf32(acc[mi][ni], af[mi], bf[ni]);
        }
        __syncthreads();
    }

    const bool dogelu  = (flags & FLAG_GELU) != 0;
    const bool doround = (flags & FLAG_ROUND) != 0;

    #pragma unroll
    for (int mi = 0; mi < 4; mi++) {
        int r0 = bm + wm * 64 + mi * 16 + lq;
        int r1 = r0 + 8;
        #pragma unroll
        for (int ni = 0; ni < 4; ni++) {
            int col = bn + wn * 32 + ni * 8 + lr * 2;
            float bx = bias[col], by = bias[col + 1];
            float* a4 = acc[mi][ni];
            #pragma unroll
            for (int half = 0; half < 2; half++) {
                int r = half ? r1 : r0;
                if (r >= M) continue;
                float vx = a4[half * 2 + 0] + bx;
                float vy = a4[half * 2 + 1] + by;
                if (resid) {
                    const float* rr = resid + (size_t)r * N + col;
                    vx += rr[0]; vy += rr[1];
                }
                if (dogelu) { vx = gelu_exact(vx); vy = gelu_exact(vy); }
                float ox = vx, oy = vy;
                if (doround) { ox = rna_tf32(vx); oy = rna_tf32(vy); }
                *(float2*)(C + (size_t)r * N + col) = make_float2(ox, oy);
                if (Cr)
                    *(float2*)(Cr + (size_t)r * N + col) =
                        make_float2(rna_tf32(vx), rna_tf32(vy));
            }
        }
    }
}

// ---------------- layernorm: fp32 out + rounded out ----------------
__global__ __launch_bounds__(128) void ln_kernel(
    const float* __restrict__ in, float* __restrict__ out, float* __restrict__ outr,
    const float* __restrict__ gamma, const float* __restrict__ beta)
{
    __shared__ float red[8];
    int row = blockIdx.x;
    int t = threadIdx.x;
    float4 v = ((const float4*)(in + (size_t)row * DEC))[t];
    float s  = v.x + v.y + v.z + v.w;
    float sq = v.x * v.x + v.y * v.y + v.z * v.z + v.w * v.w;
    #pragma unroll
    for (int off = 16; off > 0; off >>= 1) {
        s  += __shfl_xor_sync(0xffffffff, s,  off);
        sq += __shfl_xor_sync(0xffffffff, sq, off);
    }
    int w = t >> 5;
    if ((t & 31) == 0) { red[w] = s; red[4 + w] = sq; }
    __syncthreads();
    s  = red[0] + red[1] + red[2] + red[3];
    sq = red[4] + red[5] + red[6] + red[7];
    float mu = s * (1.0f / DEC);
    float var = sq * (1.0f / DEC) - mu * mu;
    float rstd = rsqrtf(var + 1e-5f);
    float4 g = ((const float4*)gamma)[t];
    float4 b = ((const float4*)beta)[t];
    float4 o;
    o.x = (v.x - mu) * rstd * g.x + b.x;
    o.y = (v.y - mu) * rstd * g.y + b.y;
    o.z = (v.z - mu) * rstd * g.z + b.z;
    o.w = (v.w - mu) * rstd * g.w + b.w;
    ((float4*)(out + (size_t)row * DEC))[t] = o;
    ((float4*)(outr + (size_t)row * DEC))[t] =
        make_float4(rna_tf32(o.x), rna_tf32(o.y), rna_tf32(o.z), rna_tf32(o.w));
}

// ---------------- attention ----------------
#define KSTRIDE 33
#define SM_K 0
#define SM_V (NPATCH * KSTRIDE)
#define SM_P (SM_V + NPATCH * HD)
#define ATTN_SMEM ((SM_P + 8 * NPATCH) * 4)

__global__ __launch_bounds__(256) void attn_kernel() {
    extern __shared__ float smf[];
    float* Ksm = smf + SM_K;
    float* Vsm = smf + SM_V;
    float* Psm = smf + SM_P;

    int bh = blockIdx.x;
    int b = bh >> 4;
    int h = bh & 15;
    const float* qkv = g_qkv + (size_t)b * (NPATCH * 3 * DEC);
    int tid = threadIdx.x;

    for (int idx = tid; idx < NPATCH * HD; idx += 256) {
        int j = idx >> 5, d = idx & 31;
        Ksm[j * KSTRIDE + d] = qkv[j * (3 * DEC) + DEC     + h * HD + d];
        Vsm[j * HD      + d] = qkv[j * (3 * DEC) + 2 * DEC + h * HD + d];
    }
    __syncthreads();

    int warp = tid >> 5, lane = tid & 31;
    const float scale = 0.17677669529663687f;

    for (int i = warp; i < NPATCH; i += 8) {
        const float* q = qkv + i * (3 * DEC) + h * HD;
        float qr[HD];
        #pragma unroll
        for (int kk = 0; kk < HD; kk++) qr[kk] = q[kk];

        float s[7];
        float mx = -1e30f;
        #pragma unroll
        for (int jj = 0; jj < 7; jj++) {
            int j = jj * 32 + lane;
            float acc = -1e30f;
            if (j < NPATCH) {
                acc = 0.f;
                #pragma unroll
                for (int kk = 0; kk < HD; kk++) acc += qr[kk] * Ksm[j * KSTRIDE + kk];
                acc *= scale;
            }
            s[jj] = acc;
            mx = fmaxf(mx, acc);
        }
        #pragma unroll
        for (int off = 16; off > 0; off >>= 1)
            mx = fmaxf(mx, __shfl_xor_sync(0xffffffff, mx, off));

        float sum = 0.f;
        #pragma unroll
        for (int jj = 0; jj < 7; jj++) {
            int j = jj * 32 + lane;
            float p = (j < NPATCH) ? __expf(s[jj] - mx) : 0.f;
            if (j < NPATCH) Psm[warp * NPATCH + j] = p;
            sum += p;
        }
        #pragma unroll
        for (int off = 16; off > 0; off >>= 1)
            sum += __shfl_xor_sync(0xffffffff, sum, off);
        float inv = 1.0f / sum;
        __syncwarp();

        const float* pp = Psm + warp * NPATCH;
        float a0 = 0.f, a1 = 0.f, a2 = 0.f, a3 = 0.f;
        for (int j = 0; j < NPATCH; j += 4) {
            a0 += pp[j]     * Vsm[j * HD + lane];
            a1 += pp[j + 1] * Vsm[(j + 1) * HD + lane];
            a2 += pp[j + 2] * Vsm[(j + 2) * HD + lane];
            a3 += pp[j + 3] * Vsm[(j + 3) * HD + lane];
        }
        float acc = (a0 + a1) + (a2 + a3);
        g_attn[((size_t)b * NPATCH + i) * DEC + h * HD + lane] = rna_tf32(acc * inv);
        __syncwarp();
    }
}

// ---------------- host launchers ----------------
static inline void launch_gemm(const float* A, const float* W, const float* bias,
                               const float* resid, float* C, float* Cr,
                               int M, int N, int K, int flags) {
    dim3 grid(N / BN, (M + BM - 1) / BM);
    gemm_tc_kernel<<<grid, 256, GEMM_SMEM>>>(A, W, bias, resid, C, Cr, M, N, K, flags);
}
static inline void launch_round(const float* src, float* dst, size_t n) {
    int n4 = (int)(n / 4);
    round_copy<<<(n4 + 255) / 256, 256>>>(src, dst, n4);
}

extern "C" void kernel_launch(void* const* d_in, const int* in_sizes, int n_in,
                              void* d_out, int out_size) {
    const float* x          = (const float*)d_in[0];
    const int*   mask       = (const int*)  d_in[1];
    const float* Wp         = (const float*)d_in[3];
    const float* bp         = (const float*)d_in[4];
    const float* We2d       = (const float*)d_in[5];
    const float* be2d       = (const float*)d_in[6];
    const float* mask_token = (const float*)d_in[7];
    const float* pos_embed  = (const float*)d_in[8];
    const float* Wqkv       = (const float*)d_in[9];
    const float* bqkv       = (const float*)d_in[10];
    const float* Wo         = (const float*)d_in[11];
    const float* bo         = (const float*)d_in[12];
    const float* ln1g       = (const float*)d_in[13];
    const float* ln1b       = (const float*)d_in[14];
    const float* W1         = (const float*)d_in[15];
    const float* b1         = (const float*)d_in[16];
    const float* W2         = (const float*)d_in[17];
    const float* b2         = (const float*)d_in[18];
    const float* ln2g       = (const float*)d_in[19];
    const float* ln2b       = (const float*)d_in[20];
    const float* Wr         = (const float*)d_in[21];
    const float* br         = (const float*)d_in[22];

    float* out = (float*)d_out;
    float* rec = out;
    float* enc = out + (size_t)ROWS_N * OUTD;

    float *p_patch, *p_encr, *p_dec, *p_h, *p_hr, *p_tmp, *p_attn, *p_qkv, *p_ffn, *p_wt;
    cudaGetSymbolAddress((void**)&p_patch, g_patch);
    cudaGetSymbolAddress((void**)&p_encr,  g_encr);
    cudaGetSymbolAddress((void**)&p_dec,   g_dec);
    cudaGetSymbolAddress((void**)&p_h,     g_h);
    cudaGetSymbolAddress((void**)&p_hr,    g_hr);
    cudaGetSymbolAddress((void**)&p_tmp,   g_tmp);
    cudaGetSymbolAddress((void**)&p_attn,  g_attn);
    cudaGetSymbolAddress((void**)&p_qkv,   g_qkv);
    cudaGetSymbolAddress((void**)&p_ffn,   g_ffn);
    cudaGetSymbolAddress((void**)&p_wt,    g_wt);

    cudaFuncSetAttribute(attn_kernel, cudaFuncAttributeMaxDynamicSharedMemorySize, ATTN_SMEM);
    cudaFuncSetAttribute(gemm_tc_kernel, cudaFuncAttributeMaxDynamicSharedMemorySize, GEMM_SMEM);

    // weight prep: elementwise RNA-tf32 round (layout unchanged [K,N])
    launch_round(Wp,   p_wt + WT_WP,  (size_t)OUTD * ENC);
    launch_round(We2d, p_wt + WT_E2D, (size_t)ENC * DEC);
    launch_round(Wqkv, p_wt + WT_QKV, (size_t)NL * DEC * 3 * DEC);
    launch_round(Wo,   p_wt + WT_O,   (size_t)NL * DEC * DEC);
    launch_round(W1,   p_wt + WT_W1,  (size_t)NL * DEC * FFN);
    launch_round(W2,   p_wt + WT_W2,  (size_t)NL * FFN * DEC);
    launch_round(Wr,   p_wt + WT_R,   (size_t)DEC * OUTD);

    scan_kernel<<<1, 64>>>(mask);
    patchify_kernel<<<ROWS_V, 256>>>(x);

    // encoder projection: C=enc (fp32 output), Cr=rounded copy for next GEMM
    launch_gemm(p_patch, p_wt + WT_WP, bp, nullptr, enc, p_encr, ROWS_V, ENC, OUTD, 0);
    launch_gemm(p_encr, p_wt + WT_E2D, be2d, nullptr, p_dec, nullptr, ROWS_V, DEC, ENC, 0);
    assemble_kernel<<<ROWS_N, 128>>>(mask_token, pos_embed);

    for (int l = 0; l < NL; l++) {
        const float* wt_qkv = p_wt + WT_QKV + (size_t)l * 3 * DEC * DEC;
        const float* wt_o   = p_wt + WT_O   + (size_t)l * DEC * DEC;
        const float* wt_1   = p_wt + WT_W1  + (size_t)l * DEC * FFN;
        const float* wt_2   = p_wt + WT_W2  + (size_t)l * FFN * DEC;
        const float* bq  = bqkv + (size_t)l * 3 * DEC;
        const float* bol = bo   + (size_t)l * DEC;
        const float* b1l = b1   + (size_t)l * FFN;
        const float* b2l = b2   + (size_t)l * DEC;

        launch_gemm(p_hr, wt_qkv, bq, nullptr, p_qkv, nullptr, ROWS_N, 3 * DEC, DEC, 0);
        attn_kernel<<<B_ * NH, 256, ATTN_SMEM>>>();
        launch_gemm(p_attn, wt_o, bol, p_h, p_tmp, nullptr, ROWS_N, DEC, DEC, 0);
        ln_kernel<<<ROWS_N, 128>>>(p_tmp, p_h, p_hr, ln1g + l * DEC, ln1b + l * DEC);
        launch_gemm(p_hr, wt_1, b1l, nullptr, p_ffn, nullptr, ROWS_N, FFN, DEC,
                    FLAG_GELU | FLAG_ROUND);
        launch_gemm(p_ffn, wt_2, b2l, p_h, p_tmp, nullptr, ROWS_N, DEC, FFN, 0);
        ln_kernel<<<ROWS_N, 128>>>(p_tmp, p_h, p_hr, ln2g + l * DEC, ln2b + l * DEC);
    }

    launch_gemm(p_hr, p_wt + WT_R, br, nullptr, rec, nullptr, ROWS_N, OUTD, DEC, 0);
}